// round 12
// baseline (speedup 1.0000x reference)
#include <cuda_runtime.h>
#include <cuda_bf16.h>
#include <cstdint>

#define D 128
#define NN 100000
#define EM 400000
#define EW 200000
#define EPS 1e-5f
#define THREADS 256
#define MTILE 64
#define AST 72                    // A tile row stride in halves (+4 banks/row skew)
#define AHB 9216                  // A half-tile: 64 rows * 72 * 2B
#define MESH_BLOCKS (EM / MTILE)          // 6250
#define WORLD_BLOCKS (EW / MTILE)         // 3125

// ---------------- smem layout (bytes), SM_TOTAL = 41984 ----------------
#define SM_A    0
#define SM_PP   18432
#define SM_CV   36864
#define SM_IDX  37888
#define SM_STAT 38400
#define SM_TOTAL 41984
#define HS_STRIDE 132             // hs: 64*132*4 = 33792 bytes at offset 0

// ---------------- device scratch ----------------
__device__ float g_agg_mesh[(size_t)NN * D];
__device__ float g_agg_world[(size_t)NN * D];
// fragment-ordered weight image: [3 mlp][8 chunk][8 ntile][4 ks][hi 32 uint4 | lo 32 uint4]
// chunk stride = 8*4*64 = 2048 uint4
__device__ uint4 g_Wfrag[3 * 256 * 64];
// node features packed, hi/lo planes: per row 32 uint4 (16 hi-quads of 8 cols, 16 lo)
__device__ uint4 g_nfp[(size_t)NN * 32];

// ---------------- helpers ----------------
__device__ __forceinline__ uint32_t smem_u32(const void* p) {
    uint32_t a;
    asm("{ .reg .u64 t; cvta.to.shared.u64 t, %1; cvt.u32.u64 %0, t; }" : "=r"(a) : "l"(p));
    return a;
}
__device__ __forceinline__ void ldsm_x4(uint32_t r[4], uint32_t addr) {
    asm volatile("ldmatrix.sync.aligned.m8n8.x4.shared.b16 {%0,%1,%2,%3}, [%4];"
        : "=r"(r[0]), "=r"(r[1]), "=r"(r[2]), "=r"(r[3]) : "r"(addr));
}
__device__ __forceinline__ void cpa16(uint32_t dst, const void* src) {
    asm volatile("cp.async.cg.shared.global [%0], [%1], 16;" :: "r"(dst), "l"(src));
}
#define CP_COMMIT() asm volatile("cp.async.commit_group;" ::: "memory")
#define CP_WAIT0()  asm volatile("cp.async.wait_group 0;" ::: "memory")
#define CP_WAIT1()  asm volatile("cp.async.wait_group 1;" ::: "memory")

#define MMA_BF16(d, a, b0, b1) \
    asm volatile("mma.sync.aligned.m16n8k16.row.col.f32.bf16.bf16.f32 " \
        "{%0,%1,%2,%3}, {%4,%5,%6,%7}, {%8,%9}, {%0,%1,%2,%3};" \
        : "+f"((d)[0]), "+f"((d)[1]), "+f"((d)[2]), "+f"((d)[3]) \
        : "r"((a)[0]), "r"((a)[1]), "r"((a)[2]), "r"((a)[3]), "r"(b0), "r"(b1))

__device__ __forceinline__ void split_pack(float x, float y, uint32_t& hp, uint32_t& lp) {
    __nv_bfloat16 h0 = __float2bfloat16(x);
    __nv_bfloat16 h1 = __float2bfloat16(y);
    __nv_bfloat16 l0 = __float2bfloat16(x - __bfloat162float(h0));
    __nv_bfloat16 l1 = __float2bfloat16(y - __bfloat162float(h1));
    hp = (uint32_t)__bfloat16_as_ushort(h0) | ((uint32_t)__bfloat16_as_ushort(h1) << 16);
    lp = (uint32_t)__bfloat16_as_ushort(l0) | ((uint32_t)__bfloat16_as_ushort(l1) << 16);
}

// one K=64 chunk: warp tile 32 rows (wM 0..1) x 32 cols (wN 0..3).
// A hi/lo via ldmatrix from smem; B via LDG.128 with compile-time immediate
// offsets off a single per-lane base pointer. pbl = bimg + chunk*2048 + wN*512 + lane.
__device__ __forceinline__ void gemm_chunk(uint32_t aH, uint32_t aL,
                                           const uint4* __restrict__ pbl,
                                           float acc[2][4][4],
                                           int wM, int lane) {
    const int i = lane & 7, sel = lane >> 3;
    const uint32_t aOff = (uint32_t)((wM * 32 + i + ((sel & 1) << 3)) * AST
                                     + ((sel >> 1) << 3)) * 2;
#pragma unroll
    for (int ks = 0; ks < 4; ks++) {
        const uint32_t kOff = aOff + ks * 32;
        uint32_t ah[2][4], al[2][4];
#pragma unroll
        for (int mt = 0; mt < 2; mt++) {
            uint32_t off = kOff + mt * (16 * AST * 2);
            ldsm_x4(ah[mt], aH + off);
            ldsm_x4(al[mt], aL + off);
        }
#pragma unroll
        for (int p = 0; p < 2; p++) {
            const uint4 bhv = __ldg(pbl + (p * 4 + ks) * 64);
            const uint4 blv = __ldg(pbl + (p * 4 + ks) * 64 + 32);
#pragma unroll
            for (int mt = 0; mt < 2; mt++) MMA_BF16(acc[mt][2 * p + 0], ah[mt], bhv.x, bhv.y);
#pragma unroll
            for (int mt = 0; mt < 2; mt++) MMA_BF16(acc[mt][2 * p + 1], ah[mt], bhv.z, bhv.w);
#pragma unroll
            for (int mt = 0; mt < 2; mt++) MMA_BF16(acc[mt][2 * p + 0], ah[mt], blv.x, blv.y);
#pragma unroll
            for (int mt = 0; mt < 2; mt++) MMA_BF16(acc[mt][2 * p + 1], ah[mt], blv.z, blv.w);
#pragma unroll
            for (int mt = 0; mt < 2; mt++) MMA_BF16(acc[mt][2 * p + 0], al[mt], bhv.x, bhv.y);
#pragma unroll
            for (int mt = 0; mt < 2; mt++) MMA_BF16(acc[mt][2 * p + 1], al[mt], bhv.z, bhv.w);
        }
    }
}

// ---------------- prep: fragment-ordered weight image + agg zero ----------------
__global__ void prep_all_kernel(const float* __restrict__ W1a, const float* __restrict__ W2a,
                                const float* __restrict__ W1b, const float* __restrict__ W2b,
                                const float* __restrict__ W1c, const float* __restrict__ W2c,
                                uint4* __restrict__ imgF,
                                float* __restrict__ z0, float* __restrict__ z1) {
    int g = blockIdx.x * 256 + threadIdx.x;
    if (g < 24576) {
        int m = g >> 13;
        int r = g & 8191;
        int cts = r >> 5;        // (c*8 + t)*4 + ks
        int l = r & 31;
        int c = cts >> 5;
        int t = (cts >> 2) & 7;
        int ks = cts & 3;
        const float* W1 = m == 0 ? W1a : (m == 1 ? W1b : W1c);
        const float* W2 = m == 0 ? W2a : (m == 1 ? W2b : W2c);
        const float* W; int bk;
        if (c < 6) { W = W1; bk = c * 64; } else { W = W2; bk = (c - 6) * 64; }
        uint32_t hw[4], lw[4];
#pragma unroll
        for (int w = 0; w < 4; w++) {
            int n = t * 16 + (l >> 2) + ((w & 2) ? 8 : 0);
            int k = bk + ks * 16 + 2 * (l & 3) + ((w & 1) ? 8 : 0);
            float v0 = W[(size_t)k * 128 + n];
            float v1 = W[(size_t)(k + 1) * 128 + n];
            split_pack(v0, v1, hw[w], lw[w]);
        }
        size_t base = ((size_t)m * 256 + cts) * 64;
        imgF[base + l]      = make_uint4(hw[0], hw[1], hw[2], hw[3]);
        imgF[base + 32 + l] = make_uint4(lw[0], lw[1], lw[2], lw[3]);
    }
    float4 z = make_float4(0.f, 0.f, 0.f, 0.f);
    size_t n4 = (size_t)NN * D / 4;
    for (size_t i = g; i < n4; i += (size_t)gridDim.x * 256) {
        ((float4*)z0)[i] = z;
        ((float4*)z1)[i] = z;
    }
}

// split fp32 node features -> hi/lo plane packed rows, unit = 8 cols
__global__ void split_kernel(const float* __restrict__ in, uint4* __restrict__ out,
                             size_t base, size_t nu) {
    size_t i = base + (size_t)blockIdx.x * blockDim.x + threadIdx.x;
    if (i < base + nu) {
        size_t row = i >> 4;
        int j = (int)(i & 15);
        const float4* p = (const float4*)(in + row * D + j * 8);
        float4 a = p[0], b = p[1];
        uint32_t h0, l0, h1, l1, h2, l2, h3, l3;
        split_pack(a.x, a.y, h0, l0);
        split_pack(a.z, a.w, h1, l1);
        split_pack(b.x, b.y, h2, l2);
        split_pack(b.z, b.w, h3, l3);
        out[row * 32 + j]      = make_uint4(h0, h1, h2, h3);
        out[row * 32 + 16 + j] = make_uint4(l0, l1, l2, l3);
    }
}

// ---------------- fused MLP+LN block body ----------------
template <bool EDGE>
__device__ __forceinline__ void mlp_block(
    const uint4* __restrict__ nfp,
    const float* __restrict__ f1, const float* __restrict__ f2,
    const float* __restrict__ res,
    const int* __restrict__ senders, const int* __restrict__ receivers,
    const uint4* __restrict__ bimg,
    const float* __restrict__ b1, const float* __restrict__ b2,
    const float* __restrict__ gam, const float* __restrict__ bet,
    float* __restrict__ aggOut, float* __restrict__ out,
    int nRows, int r0, char* sm) {

    float* cv   = (float*)(sm + SM_CV);
    int*   sidx = (int*)(sm + SM_IDX);
    int*   ridx = sidx + MTILE;
    float* hs   = (float*)sm;

    const uint32_t smb = smem_u32(sm);
    const int tid = threadIdx.x;
    const int lane = tid & 31;
    const int wid = tid >> 5;
    const int wM = wid >> 2;       // 0..1
    const int wN = wid & 3;        // 0..3
    const int g4 = lane >> 2, cl = lane & 3;

    if (tid < 64) {
        int rr = r0 + tid;
        if (rr >= nRows) rr = nRows - 1;
        sidx[tid] = EDGE ? senders[rr] : rr;
        ridx[tid] = EDGE ? receivers[rr] : 0;
    } else if (tid >= 128) {
        int t = tid - 128;
        cv[t]       = b1[t];
        cv[128 + t] = b2[t];
    }
    __syncthreads();

    const uint32_t bufA[2] = { smb + SM_A, smb + SM_PP };
    const uint32_t bufOff[2] = { SM_A, SM_PP };
    // per-lane B base within an MLP image (chunk stride 2048 uint4)
    const uint4* pblBase = bimg + wN * 512 + lane;

    auto prefetch = [&](int c, int bi) {
        const int src = c >> 1;
        const bool packed = EDGE ? (src < 2) : (src == 0);
        if (packed) {
            const int q0 = (c & 1) * 8;
            const int* idx = (src == 0) ? sidx : ridx;
#pragma unroll
            for (int jj = 0; jj < 2; jj++) {
                int e = jj * THREADS + tid;        // 0..511
                int row = e >> 3;
                int j8 = e & 7;
                const uint4* p = nfp + (size_t)idx[row] * 32 + q0 + j8;
                uint32_t off = (uint32_t)(row * AST + j8 * 8) * 2;
                cpa16(bufA[bi] + off, p);               // hi plane
                cpa16(bufA[bi] + AHB + off, p + 16);    // lo plane
            }
        } else {
            const float* f = (EDGE || src == 1) ? f1 : f2;
            const int col0 = (c & 1) * 64;
#pragma unroll
            for (int j = 0; j < 4; j++) {
                int e = j * THREADS + tid;
                int row = e >> 4, f4 = e & 15;
                int gr = r0 + row;
                if (gr >= nRows) gr = nRows - 1;
                float4 v = *(const float4*)(f + (size_t)gr * D + col0 + f4 * 4);
                uint32_t h0, l0, h1, l1;
                split_pack(v.x, v.y, h0, l0);
                split_pack(v.z, v.w, h1, l1);
                uint32_t off = (uint32_t)(row * AST + f4 * 4) * 2;
                *(uint2*)(sm + bufOff[bi] + off) = make_uint2(h0, h1);
                *(uint2*)(sm + bufOff[bi] + AHB + off) = make_uint2(l0, l1);
            }
        }
    };

    float acc[2][4][4];
#pragma unroll
    for (int mt = 0; mt < 2; mt++)
#pragma unroll
        for (int nt = 0; nt < 4; nt++)
#pragma unroll
            for (int j = 0; j < 4; j++) acc[mt][nt][j] = 0.f;

    // ================= GEMM1: 6 K-chunks of 64, A pipelined; B direct-LDG =================
    prefetch(0, 0);
    CP_COMMIT();
    for (int c = 0; c < 6; c++) {
        if (c < 5) { prefetch(c + 1, (c + 1) & 1); CP_COMMIT(); CP_WAIT1(); }
        else       { CP_WAIT0(); }
        __syncthreads();
        gemm_chunk(bufA[c & 1], bufA[c & 1] + AHB, pblBase + c * 2048, acc, wM, lane);
        __syncthreads();
    }

    // ================= h = relu(D1 + b1) -> bf16 hi/lo into H =================
#pragma unroll
    for (int mt = 0; mt < 2; mt++)
#pragma unroll
        for (int nt = 0; nt < 4; nt++)
#pragma unroll
            for (int h = 0; h < 2; h++) {
                int row = wM * 32 + mt * 16 + h * 8 + g4;
                int col = wN * 32 + nt * 8 + 2 * cl;
                float v0 = fmaxf(acc[mt][nt][2 * h]     + cv[col],     0.f);
                float v1 = fmaxf(acc[mt][nt][2 * h + 1] + cv[col + 1], 0.f);
                uint32_t hp, lp;
                split_pack(v0, v1, hp, lp);
                int hc = col >> 6;
                uint32_t off = (uint32_t)(row * AST + (col & 63)) * 2;
                *(uint32_t*)(sm + hc * AHB + off) = hp;
                *(uint32_t*)(sm + SM_PP + hc * AHB + off) = lp;
            }
#pragma unroll
    for (int mt = 0; mt < 2; mt++)
#pragma unroll
        for (int nt = 0; nt < 4; nt++)
#pragma unroll
            for (int j = 0; j < 4; j++) acc[mt][nt][j] = 0.f;
    __syncthreads();

    // ================= GEMM2: 2 K-chunks of 64 (A = H, B chunks 6-7) =================
#pragma unroll
    for (int c2 = 0; c2 < 2; c2++) {
        gemm_chunk(smb + c2 * AHB, smb + SM_PP + c2 * AHB,
                   pblBase + (6 + c2) * 2048, acc, wM, lane);
    }
    __syncthreads();

    // ================= bias2 + LN stats =================
    float* statS = (float*)(sm + SM_STAT);          // [4][64]
    float* statQ = statS + 256;
    float* meanv = statQ + 256;                     // [64]
    float* rstdv = meanv + 64;
    float* sg    = rstdv + 64;                      // [128]
    float* sb    = sg + 128;

#pragma unroll
    for (int mt = 0; mt < 2; mt++)
#pragma unroll
        for (int nt = 0; nt < 4; nt++)
#pragma unroll
            for (int j = 0; j < 4; j++) {
                int col = wN * 32 + nt * 8 + 2 * cl + (j & 1);
                acc[mt][nt][j] += cv[128 + col];
            }
    if (tid < 128) {
        sg[tid] = gam[tid];
        sb[tid] = bet[tid];
    }
#pragma unroll
    for (int mt = 0; mt < 2; mt++)
#pragma unroll
        for (int h = 0; h < 2; h++) {
            float s = 0.f, q = 0.f;
#pragma unroll
            for (int nt = 0; nt < 4; nt++) {
                float v0 = acc[mt][nt][2 * h], v1 = acc[mt][nt][2 * h + 1];
                s += v0 + v1;
                q += v0 * v0 + v1 * v1;
            }
            s += __shfl_xor_sync(0xffffffffu, s, 1);
            s += __shfl_xor_sync(0xffffffffu, s, 2);
            q += __shfl_xor_sync(0xffffffffu, q, 1);
            q += __shfl_xor_sync(0xffffffffu, q, 2);
            if (cl == 0) {
                int r = wM * 32 + mt * 16 + h * 8 + g4;
                statS[wN * 64 + r] = s;
                statQ[wN * 64 + r] = q;
            }
        }
    __syncthreads();
    if (tid < 64) {
        float s = statS[tid] + statS[64 + tid] + statS[128 + tid] + statS[192 + tid];
        float q = statQ[tid] + statQ[64 + tid] + statQ[128 + tid] + statQ[192 + tid];
        float mean = s * (1.f / D);
        float var = q * (1.f / D) - mean * mean;
        meanv[tid] = mean;
        rstdv[tid] = rsqrtf(var + EPS);
    }
    __syncthreads();

    // ================= LN apply -> hs =================
#pragma unroll
    for (int mt = 0; mt < 2; mt++)
#pragma unroll
        for (int nt = 0; nt < 4; nt++)
#pragma unroll
            for (int j = 0; j < 4; j++) {
                int row = wM * 32 + mt * 16 + ((j >> 1) << 3) + g4;
                int col = wN * 32 + nt * 8 + 2 * cl + (j & 1);
                float y = sg[col] * (acc[mt][nt][j] - meanv[row]) * rstdv[row] + sb[col];
                hs[row * HS_STRIDE + col] = y;
            }
    __syncthreads();

    // ================= epilogue =================
#pragma unroll
    for (int j = 0; j < (MTILE * 32) / THREADS; j++) {
        int e = j * THREADS + tid;
        int r = e >> 5;
        int q = e & 31;
        int gr = r0 + r;
        if (gr < nRows) {
            float4 y = *(const float4*)&hs[r * HS_STRIDE + q * 4];
            size_t gi = (size_t)gr * D + q * 4;
            if (EDGE) {
                atomicAdd((float4*)&aggOut[(size_t)ridx[r] * D + q * 4], y);
            }
            float4 rv = *(const float4*)&res[gi];
            float4 o = make_float4(y.x + rv.x, y.y + rv.y, y.z + rv.z, y.w + rv.w);
            *(float4*)&out[gi] = o;
        }
    }
}

// ---------------- kernels ----------------
__global__ void __launch_bounds__(THREADS, 4)
edge_kernel(const uint4* __restrict__ nfp,
            const float* __restrict__ mf, const float* __restrict__ wf,
            const int* __restrict__ msnd, const int* __restrict__ mrcv,
            const int* __restrict__ wsnd, const int* __restrict__ wrcv,
            const uint4* __restrict__ fragME, const uint4* __restrict__ fragWE,
            const float* __restrict__ meb1, const float* __restrict__ meb2,
            const float* __restrict__ meg,  const float* __restrict__ mebt,
            const float* __restrict__ web1, const float* __restrict__ web2,
            const float* __restrict__ weg,  const float* __restrict__ webt,
            float* __restrict__ aggM, float* __restrict__ aggW,
            float* __restrict__ outM, float* __restrict__ outW) {
    extern __shared__ char sm[];
    bool mesh = blockIdx.x < MESH_BLOCKS;
    int r0 = (mesh ? blockIdx.x : blockIdx.x - MESH_BLOCKS) * MTILE;
    mlp_block<true>(nfp,
                    mesh ? mf : wf, nullptr, mesh ? mf : wf,
                    mesh ? msnd : wsnd, mesh ? mrcv : wrcv,
                    mesh ? fragME : fragWE,
                    mesh ? meb1 : web1, mesh ? meb2 : web2,
                    mesh ? meg : weg,   mesh ? mebt : webt,
                    mesh ? aggM : aggW, mesh ? outM : outW,
                    mesh ? EM : EW, r0, sm);
}

__global__ void __launch_bounds__(THREADS, 4)
node_kernel(const uint4* __restrict__ nfp,
            const float* __restrict__ aggM, const float* __restrict__ aggW,
            const float* __restrict__ nf,
            const uint4* __restrict__ fragNM,
            const float* __restrict__ b1, const float* __restrict__ b2,
            const float* __restrict__ gam, const float* __restrict__ bet,
            float* __restrict__ out) {
    extern __shared__ char sm[];
    mlp_block<false>(nfp, aggM, aggW, nf, nullptr, nullptr,
                     fragNM, b1, b2, gam, bet, nullptr, out, NN,
                     blockIdx.x * MTILE, sm);
}

// ---------------- launch ----------------
extern "C" void kernel_launch(void* const* d_in, const int* in_sizes, int n_in,
                              void* d_out, int out_size) {
    (void)in_sizes; (void)n_in; (void)out_size;
    const float* nf   = (const float*)d_in[0];
    const int*   msnd = (const int*)d_in[1];
    const int*   mrcv = (const int*)d_in[2];
    const float* mf   = (const float*)d_in[3];
    const int*   wsnd = (const int*)d_in[4];
    const int*   wrcv = (const int*)d_in[5];
    const float* wf   = (const float*)d_in[6];

    const float* meW1 = (const float*)d_in[7];
    const float* meb1 = (const float*)d_in[8];
    const float* meW2 = (const float*)d_in[9];
    const float* meb2 = (const float*)d_in[10];
    const float* meg  = (const float*)d_in[11];
    const float* mebt = (const float*)d_in[12];

    const float* weW1 = (const float*)d_in[13];
    const float* web1 = (const float*)d_in[14];
    const float* weW2 = (const float*)d_in[15];
    const float* web2 = (const float*)d_in[16];
    const float* weg  = (const float*)d_in[17];
    const float* webt = (const float*)d_in[18];

    const float* nmW1 = (const float*)d_in[19];
    const float* nmb1 = (const float*)d_in[20];
    const float* nmW2 = (const float*)d_in[21];
    const float* nmb2 = (const float*)d_in[22];
    const float* nmg  = (const float*)d_in[23];
    const float* nmbt = (const float*)d_in[24];

    float* out       = (float*)d_out;
    float* out_nodes = out;
    float* out_mesh  = out + (size_t)NN * D;
    float* out_world = out_mesh + (size_t)EM * D;

    float* aggM = nullptr;  float* aggW = nullptr;
    uint4* imgF = nullptr;  uint4* nfp = nullptr;
    cudaGetSymbolAddress((void**)&aggM, g_agg_mesh);
    cudaGetSymbolAddress((void**)&aggW, g_agg_world);
    cudaGetSymbolAddress((void**)&imgF, g_Wfrag);
    cudaGetSymbolAddress((void**)&nfp, g_nfp);
    uint4* fragME = imgF;
    uint4* fragWE = imgF + 16384;
    uint4* fragNM = imgF + 32768;

    cudaFuncSetAttribute(edge_kernel, cudaFuncAttributeMaxDynamicSharedMemorySize, SM_TOTAL);
    cudaFuncSetAttribute(node_kernel, cudaFuncAttributeMaxDynamicSharedMemorySize, SM_TOTAL);

    // #0: fragment-ordered weight image + agg zero
    prep_all_kernel<<<256, 256>>>(meW1, meW2, weW1, weW2, nmW1, nmW2, imgF, aggM, aggW);
    // #1, #2: split node features into hi/lo planes (two halves)
    {
        size_t nu = (size_t)NN * 16;
        size_t h0 = nu / 2, h1 = nu - h0;
        split_kernel<<<(int)((h0 + 255) / 256), 256>>>(nf, nfp, 0, h0);
        split_kernel<<<(int)((h1 + 255) / 256), 256>>>(nf, nfp, h0, h1);
    }
    // #3: fused mesh+world edge kernel (profiled)
    edge_kernel<<<MESH_BLOCKS + WORLD_BLOCKS, THREADS, SM_TOTAL>>>(
        nfp, mf, wf, msnd, mrcv, wsnd, wrcv,
        fragME, fragWE, meb1, meb2, meg, mebt, web1, web2, weg, webt,
        aggM, aggW, out_mesh, out_world);
    // #4: node kernel
    node_kernel<<<(NN + MTILE - 1) / MTILE, THREADS, SM_TOTAL>>>(
        nfp, aggM, aggW, nf, fragNM, nmb1, nmb2, nmg, nmbt, out_nodes);
}

// round 13
// speedup vs baseline: 1.2771x; 1.2771x over previous
#include <cuda_runtime.h>
#include <cuda_bf16.h>
#include <cstdint>

#define D 128
#define NN 100000
#define EM 400000
#define EW 200000
#define EPS 1e-5f
#define THREADS 256
#define MTILE 64
#define AST 72                    // A tile row stride in halves (+4 banks/row skew)
#define AHB 9216                  // A half-tile: 64 rows * 72 * 2B
#define MESH_BLOCKS (EM / MTILE)          // 6250
#define WORLD_BLOCKS (EW / MTILE)         // 3125
#define NODE_TILES ((NN + MTILE - 1) / MTILE) // 1563

// ---------------- smem layout (bytes), SM_TOTAL = 41984 -> 3 CTAs/SM ----------------
#define SM_A    0
#define SM_PP   18432
#define SM_CV   36864
#define SM_IDX  37888
#define SM_STAT 38400
#define SM_TOTAL 41984
#define HS_STRIDE 132             // hs: 64*132*4 = 33792 bytes at offset 0

// ---------------- device scratch ----------------
__device__ float g_agg_mesh[(size_t)NN * D];
__device__ float g_agg_world[(size_t)NN * D];
// fragment-ordered weight image: [3 mlp][8 chunk][8 ntile][4 ks][hi 32 uint4 | lo 32 uint4]
// chunk stride = 2048 uint4
__device__ uint4 g_Wfrag[3 * 256 * 64];
// precomputed first-layer partials: P = nf @ W1x  (fp32)
__device__ float g_Pam[(size_t)NN * D];   // mesh W1a  (sender part)
__device__ float g_Pbm[(size_t)NN * D];   // mesh W1b  (receiver part)
__device__ float g_Paw[(size_t)NN * D];   // world W1a
__device__ float g_Pbw[(size_t)NN * D];   // world W1b
__device__ float g_Pan[(size_t)NN * D];   // node W1a  (nf part)

// ---------------- helpers ----------------
__device__ __forceinline__ uint32_t smem_u32(const void* p) {
    uint32_t a;
    asm("{ .reg .u64 t; cvta.to.shared.u64 t, %1; cvt.u32.u64 %0, t; }" : "=r"(a) : "l"(p));
    return a;
}
__device__ __forceinline__ void ldsm_x4(uint32_t r[4], uint32_t addr) {
    asm volatile("ldmatrix.sync.aligned.m8n8.x4.shared.b16 {%0,%1,%2,%3}, [%4];"
        : "=r"(r[0]), "=r"(r[1]), "=r"(r[2]), "=r"(r[3]) : "r"(addr));
}
#define MMA_BF16(d, a, b0, b1) \
    asm volatile("mma.sync.aligned.m16n8k16.row.col.f32.bf16.bf16.f32 " \
        "{%0,%1,%2,%3}, {%4,%5,%6,%7}, {%8,%9}, {%0,%1,%2,%3};" \
        : "+f"((d)[0]), "+f"((d)[1]), "+f"((d)[2]), "+f"((d)[3]) \
        : "r"((a)[0]), "r"((a)[1]), "r"((a)[2]), "r"((a)[3]), "r"(b0), "r"(b1))

__device__ __forceinline__ void split_pack(float x, float y, uint32_t& hp, uint32_t& lp) {
    __nv_bfloat16 h0 = __float2bfloat16(x);
    __nv_bfloat16 h1 = __float2bfloat16(y);
    __nv_bfloat16 l0 = __float2bfloat16(x - __bfloat162float(h0));
    __nv_bfloat16 l1 = __float2bfloat16(y - __bfloat162float(h1));
    hp = (uint32_t)__bfloat16_as_ushort(h0) | ((uint32_t)__bfloat16_as_ushort(h1) << 16);
    lp = (uint32_t)__bfloat16_as_ushort(l0) | ((uint32_t)__bfloat16_as_ushort(l1) << 16);
}

// one K=64 chunk: warp tile 32x32; A hi/lo via ldmatrix, B via LDG.128 from
// fragment image. pbl = img + chunk*2048 + wN*512 + lane.
__device__ __forceinline__ void gemm_chunk(uint32_t aH, uint32_t aL,
                                           const uint4* __restrict__ pbl,
                                           float acc[2][4][4],
                                           int wM, int lane) {
    const int i = lane & 7, sel = lane >> 3;
    const uint32_t aOff = (uint32_t)((wM * 32 + i + ((sel & 1) << 3)) * AST
                                     + ((sel >> 1) << 3)) * 2;
#pragma unroll
    for (int ks = 0; ks < 4; ks++) {
        const uint32_t kOff = aOff + ks * 32;
        uint32_t ah[2][4], al[2][4];
#pragma unroll
        for (int mt = 0; mt < 2; mt++) {
            uint32_t off = kOff + mt * (16 * AST * 2);
            ldsm_x4(ah[mt], aH + off);
            ldsm_x4(al[mt], aL + off);
        }
#pragma unroll
        for (int p = 0; p < 2; p++) {
            const uint4 bhv = __ldg(pbl + (p * 4 + ks) * 64);
            const uint4 blv = __ldg(pbl + (p * 4 + ks) * 64 + 32);
#pragma unroll
            for (int mt = 0; mt < 2; mt++) MMA_BF16(acc[mt][2 * p + 0], ah[mt], bhv.x, bhv.y);
#pragma unroll
            for (int mt = 0; mt < 2; mt++) MMA_BF16(acc[mt][2 * p + 1], ah[mt], bhv.z, bhv.w);
#pragma unroll
            for (int mt = 0; mt < 2; mt++) MMA_BF16(acc[mt][2 * p + 0], ah[mt], blv.x, blv.y);
#pragma unroll
            for (int mt = 0; mt < 2; mt++) MMA_BF16(acc[mt][2 * p + 1], ah[mt], blv.z, blv.w);
#pragma unroll
            for (int mt = 0; mt < 2; mt++) MMA_BF16(acc[mt][2 * p + 0], al[mt], bhv.x, bhv.y);
#pragma unroll
            for (int mt = 0; mt < 2; mt++) MMA_BF16(acc[mt][2 * p + 1], al[mt], bhv.z, bhv.w);
        }
    }
}

// gather 64 fp32 rows x 64 cols from f (row-major, stride D), split to bf16
// hi/lo planes in smem buffer (plain stores)
__device__ __forceinline__ void stage_f32(const float* __restrict__ f, int col0,
                                          int r0, int nRows, char* sm, int bufOff,
                                          int tid) {
#pragma unroll
    for (int j = 0; j < 4; j++) {
        int e = j * THREADS + tid;
        int row = e >> 4, f4 = e & 15;
        int gr = r0 + row;
        if (gr >= nRows) gr = nRows - 1;
        float4 v = *(const float4*)(f + (size_t)gr * D + col0 + f4 * 4);
        uint32_t h0, l0, h1, l1;
        split_pack(v.x, v.y, h0, l0);
        split_pack(v.z, v.w, h1, l1);
        uint32_t off = (uint32_t)(row * AST + f4 * 4) * 2;
        *(uint2*)(sm + bufOff + off) = make_uint2(h0, h1);
        *(uint2*)(sm + bufOff + AHB + off) = make_uint2(l0, l1);
    }
}

// ---------------- prep: fragment-ordered weight image + agg zero ----------------
__global__ void prep_all_kernel(const float* __restrict__ W1a, const float* __restrict__ W2a,
                                const float* __restrict__ W1b, const float* __restrict__ W2b,
                                const float* __restrict__ W1c, const float* __restrict__ W2c,
                                uint4* __restrict__ imgF,
                                float* __restrict__ z0, float* __restrict__ z1) {
    int g = blockIdx.x * 256 + threadIdx.x;
    if (g < 24576) {
        int m = g >> 13;
        int r = g & 8191;
        int cts = r >> 5;        // (c*8 + t)*4 + ks
        int l = r & 31;
        int c = cts >> 5;
        int t = (cts >> 2) & 7;
        int ks = cts & 3;
        const float* W1 = m == 0 ? W1a : (m == 1 ? W1b : W1c);
        const float* W2 = m == 0 ? W2a : (m == 1 ? W2b : W2c);
        const float* W; int bk;
        if (c < 6) { W = W1; bk = c * 64; } else { W = W2; bk = (c - 6) * 64; }
        uint32_t hw[4], lw[4];
#pragma unroll
        for (int w = 0; w < 4; w++) {
            int n = t * 16 + (l >> 2) + ((w & 2) ? 8 : 0);
            int k = bk + ks * 16 + 2 * (l & 3) + ((w & 1) ? 8 : 0);
            float v0 = W[(size_t)k * 128 + n];
            float v1 = W[(size_t)(k + 1) * 128 + n];
            split_pack(v0, v1, hw[w], lw[w]);
        }
        size_t base = ((size_t)m * 256 + cts) * 64;
        imgF[base + l]      = make_uint4(hw[0], hw[1], hw[2], hw[3]);
        imgF[base + 32 + l] = make_uint4(lw[0], lw[1], lw[2], lw[3]);
    }
    float4 z = make_float4(0.f, 0.f, 0.f, 0.f);
    size_t n4 = (size_t)NN * D / 4;
    for (size_t i = g; i < n4; i += (size_t)gridDim.x * 256) {
        ((float4*)z0)[i] = z;
        ((float4*)z1)[i] = z;
    }
}

// ---------------- precompute: P = nf @ W1x for (Pa, Pb) of one MLP ----------------
// combo: 0 = mesh (Pa,Pb), 1 = world (Pa,Pb), 2 = node (Pa only).
__global__ void __launch_bounds__(THREADS, 3)
precompute_kernel(const float* __restrict__ nf,
                  const uint4* __restrict__ imgF,
                  float* __restrict__ Pam, float* __restrict__ Pbm,
                  float* __restrict__ Paw, float* __restrict__ Pbw,
                  float* __restrict__ Pan,
                  int comboBase) {
    extern __shared__ char sm[];
    int bid = blockIdx.x;
    int combo = comboBase + bid / NODE_TILES;
    int r0 = (bid % NODE_TILES) * MTILE;

    const uint4* img = imgF + (size_t)(combo == 0 ? 0 : (combo == 1 ? 1 : 2)) * 16384;
    float* Pa = combo == 0 ? Pam : (combo == 1 ? Paw : Pan);
    float* Pb = combo == 0 ? Pbm : (combo == 1 ? Pbw : nullptr);

    const uint32_t smb = smem_u32(sm);
    const int tid = threadIdx.x;
    const int lane = tid & 31;
    const int wid = tid >> 5;
    const int wM = wid >> 2;
    const int wN = wid & 3;
    const int g4 = lane >> 2, cl = lane & 3;
    const uint4* pblBase = img + wN * 512 + lane;

    // stage nf rows (cols 0..63 -> buf0, 64..127 -> buf1)
    stage_f32(nf, 0,  r0, NN, sm, SM_A,  tid);
    stage_f32(nf, 64, r0, NN, sm, SM_PP, tid);
    __syncthreads();

    for (int pass = 0; pass < 2; pass++) {
        if (pass == 1 && Pb == nullptr) break;
        float acc[2][4][4];
#pragma unroll
        for (int mt = 0; mt < 2; mt++)
#pragma unroll
            for (int nt = 0; nt < 4; nt++)
#pragma unroll
                for (int j = 0; j < 4; j++) acc[mt][nt][j] = 0.f;
        const int c0 = pass * 2;     // image chunks 0,1 (W1a) or 2,3 (W1b)
        gemm_chunk(smb + SM_A,  smb + SM_A + AHB,  pblBase + (c0 + 0) * 2048, acc, wM, lane);
        gemm_chunk(smb + SM_PP, smb + SM_PP + AHB, pblBase + (c0 + 1) * 2048, acc, wM, lane);
        float* P = pass == 0 ? Pa : Pb;
        // direct fragment store (float2, quad-coalesced into 32B sectors)
#pragma unroll
        for (int mt = 0; mt < 2; mt++)
#pragma unroll
            for (int nt = 0; nt < 4; nt++)
#pragma unroll
                for (int h = 0; h < 2; h++) {
                    int row = wM * 32 + mt * 16 + h * 8 + g4;
                    int col = wN * 32 + nt * 8 + 2 * cl;
                    int gr = r0 + row;
                    if (gr < NN)
                        *(float2*)&P[(size_t)gr * D + col] =
                            make_float2(acc[mt][nt][2 * h], acc[mt][nt][2 * h + 1]);
                }
    }
}

// ---------------- fused MLP+LN block body ----------------
// EDGE:  GEMM1 = 2 chunks of ef @ W1c (image chunks 4,5); then acc += Pa[s] + Pb[r].
// !EDGE: GEMM1 = 4 chunks (aggM -> img 2,3; aggW -> img 4,5); then acc += Pa[row].
template <bool EDGE>
__device__ __forceinline__ void mlp_block(
    const float* __restrict__ f1, const float* __restrict__ f2,
    const float* __restrict__ res,
    const float* __restrict__ Pa, const float* __restrict__ Pb,
    const int* __restrict__ senders, const int* __restrict__ receivers,
    const uint4* __restrict__ bimg,
    const float* __restrict__ b1, const float* __restrict__ b2,
    const float* __restrict__ gam, const float* __restrict__ bet,
    float* __restrict__ aggOut, float* __restrict__ out,
    int nRows, int r0, char* sm) {

    float* cv   = (float*)(sm + SM_CV);
    int*   sidx = (int*)(sm + SM_IDX);
    int*   ridx = sidx + MTILE;
    float* hs   = (float*)sm;

    const uint32_t smb = smem_u32(sm);
    const int tid = threadIdx.x;
    const int lane = tid & 31;
    const int wid = tid >> 5;
    const int wM = wid >> 2;       // 0..1
    const int wN = wid & 3;        // 0..3
    const int g4 = lane >> 2, cl = lane & 3;

    if (tid < 64) {
        int rr = r0 + tid;
        if (rr >= nRows) rr = nRows - 1;
        sidx[tid] = EDGE ? senders[rr] : rr;
        ridx[tid] = EDGE ? receivers[rr] : rr;
    } else if (tid >= 128) {
        int t = tid - 128;
        cv[t]       = b1[t];
        cv[128 + t] = b2[t];
    }
    __syncthreads();

    const int bufOff[2] = { SM_A, SM_PP };
    const uint4* pblBase = bimg + wN * 512 + lane;

    float acc[2][4][4];
#pragma unroll
    for (int mt = 0; mt < 2; mt++)
#pragma unroll
        for (int nt = 0; nt < 4; nt++)
#pragma unroll
            for (int j = 0; j < 4; j++) acc[mt][nt][j] = 0.f;

    // ================= GEMM1 =================
    const int NC = EDGE ? 2 : 4;            // chunk count
    const int IC0 = EDGE ? 4 : 2;           // first image chunk
    stage_f32(EDGE ? res : f1, 0, r0, nRows, sm, SM_A, tid);
    __syncthreads();
    for (int c = 0; c < NC; c++) {
        if (c + 1 < NC) {
            const float* f = EDGE ? res : ((c + 1) < 2 ? f1 : f2);
            stage_f32(f, ((c + 1) & 1) * 64, r0, nRows, sm, bufOff[(c + 1) & 1], tid);
        }
        // NOTE: staging for c+1 writes the OTHER buffer; gemm reads buffer c.
        __syncthreads();
        gemm_chunk(smb + bufOff[c & 1], smb + bufOff[c & 1] + AHB,
                   pblBase + (IC0 + c) * 2048, acc, wM, lane);
        __syncthreads();
    }

    // ================= acc += P gathers; h = relu(acc + b1) -> H =================
#pragma unroll
    for (int mt = 0; mt < 2; mt++)
#pragma unroll
        for (int nt = 0; nt < 4; nt++)
#pragma unroll
            for (int h = 0; h < 2; h++) {
                int row = wM * 32 + mt * 16 + h * 8 + g4;
                int col = wN * 32 + nt * 8 + 2 * cl;
                float2 pa = *(const float2*)&Pa[(size_t)sidx[row] * D + col];
                float v0 = acc[mt][nt][2 * h]     + pa.x;
                float v1 = acc[mt][nt][2 * h + 1] + pa.y;
                if (EDGE) {
                    float2 pb = *(const float2*)&Pb[(size_t)ridx[row] * D + col];
                    v0 += pb.x;
                    v1 += pb.y;
                }
                v0 = fmaxf(v0 + cv[col],     0.f);
                v1 = fmaxf(v1 + cv[col + 1], 0.f);
                uint32_t hp, lp;
                split_pack(v0, v1, hp, lp);
                int hc = col >> 6;
                uint32_t off = (uint32_t)(row * AST + (col & 63)) * 2;
                *(uint32_t*)(sm + hc * AHB + off) = hp;
                *(uint32_t*)(sm + SM_PP + hc * AHB + off) = lp;
            }
#pragma unroll
    for (int mt = 0; mt < 2; mt++)
#pragma unroll
        for (int nt = 0; nt < 4; nt++)
#pragma unroll
            for (int j = 0; j < 4; j++) acc[mt][nt][j] = 0.f;
    __syncthreads();

    // ================= GEMM2: image chunks 6,7 (A = H) =================
#pragma unroll
    for (int c2 = 0; c2 < 2; c2++) {
        gemm_chunk(smb + c2 * AHB, smb + SM_PP + c2 * AHB,
                   pblBase + (6 + c2) * 2048, acc, wM, lane);
    }
    __syncthreads();

    // ================= bias2 + LN stats =================
    float* statS = (float*)(sm + SM_STAT);          // [4][64]
    float* statQ = statS + 256;
    float* meanv = statQ + 256;                     // [64]
    float* rstdv = meanv + 64;
    float* sg    = rstdv + 64;                      // [128]
    float* sb    = sg + 128;

#pragma unroll
    for (int mt = 0; mt < 2; mt++)
#pragma unroll
        for (int nt = 0; nt < 4; nt++)
#pragma unroll
            for (int j = 0; j < 4; j++) {
                int col = wN * 32 + nt * 8 + 2 * cl + (j & 1);
                acc[mt][nt][j] += cv[128 + col];
            }
    if (tid < 128) {
        sg[tid] = gam[tid];
        sb[tid] = bet[tid];
    }
#pragma unroll
    for (int mt = 0; mt < 2; mt++)
#pragma unroll
        for (int h = 0; h < 2; h++) {
            float s = 0.f, q = 0.f;
#pragma unroll
            for (int nt = 0; nt < 4; nt++) {
                float v0 = acc[mt][nt][2 * h], v1 = acc[mt][nt][2 * h + 1];
                s += v0 + v1;
                q += v0 * v0 + v1 * v1;
            }
            s += __shfl_xor_sync(0xffffffffu, s, 1);
            s += __shfl_xor_sync(0xffffffffu, s, 2);
            q += __shfl_xor_sync(0xffffffffu, q, 1);
            q += __shfl_xor_sync(0xffffffffu, q, 2);
            if (cl == 0) {
                int r = wM * 32 + mt * 16 + h * 8 + g4;
                statS[wN * 64 + r] = s;
                statQ[wN * 64 + r] = q;
            }
        }
    __syncthreads();
    if (tid < 64) {
        float s = statS[tid] + statS[64 + tid] + statS[128 + tid] + statS[192 + tid];
        float q = statQ[tid] + statQ[64 + tid] + statQ[128 + tid] + statQ[192 + tid];
        float mean = s * (1.f / D);
        float var = q * (1.f / D) - mean * mean;
        meanv[tid] = mean;
        rstdv[tid] = rsqrtf(var + EPS);
    }
    __syncthreads();

    // ================= LN apply -> hs =================
#pragma unroll
    for (int mt = 0; mt < 2; mt++)
#pragma unroll
        for (int nt = 0; nt < 4; nt++)
#pragma unroll
            for (int j = 0; j < 4; j++) {
                int row = wM * 32 + mt * 16 + ((j >> 1) << 3) + g4;
                int col = wN * 32 + nt * 8 + 2 * cl + (j & 1);
                float y = sg[col] * (acc[mt][nt][j] - meanv[row]) * rstdv[row] + sb[col];
                hs[row * HS_STRIDE + col] = y;
            }
    __syncthreads();

    // ================= epilogue =================
#pragma unroll
    for (int j = 0; j < (MTILE * 32) / THREADS; j++) {
        int e = j * THREADS + tid;
        int r = e >> 5;
        int q = e & 31;
        int gr = r0 + r;
        if (gr < nRows) {
            float4 y = *(const float4*)&hs[r * HS_STRIDE + q * 4];
            size_t gi = (size_t)gr * D + q * 4;
            if (EDGE) {
                atomicAdd((float4*)&aggOut[(size_t)ridx[r] * D + q * 4], y);
            }
            float4 rv = *(const float4*)&res[gi];
            float4 o = make_float4(y.x + rv.x, y.y + rv.y, y.z + rv.z, y.w + rv.w);
            *(float4*)&out[gi] = o;
        }
    }
}

// ---------------- kernels ----------------
__global__ void __launch_bounds__(THREADS, 3)
edge_kernel(const float* __restrict__ mf, const float* __restrict__ wf,
            const int* __restrict__ msnd, const int* __restrict__ mrcv,
            const int* __restrict__ wsnd, const int* __restrict__ wrcv,
            const uint4* __restrict__ fragME, const uint4* __restrict__ fragWE,
            const float* __restrict__ Pam, const float* __restrict__ Pbm,
            const float* __restrict__ Paw, const float* __restrict__ Pbw,
            const float* __restrict__ meb1, const float* __restrict__ meb2,
            const float* __restrict__ meg,  const float* __restrict__ mebt,
            const float* __restrict__ web1, const float* __restrict__ web2,
            const float* __restrict__ weg,  const float* __restrict__ webt,
            float* __restrict__ aggM, float* __restrict__ aggW,
            float* __restrict__ outM, float* __restrict__ outW) {
    extern __shared__ char sm[];
    bool mesh = blockIdx.x < MESH_BLOCKS;
    int r0 = (mesh ? blockIdx.x : blockIdx.x - MESH_BLOCKS) * MTILE;
    mlp_block<true>(mesh ? mf : wf, nullptr, mesh ? mf : wf,
                    mesh ? Pam : Paw, mesh ? Pbm : Pbw,
                    mesh ? msnd : wsnd, mesh ? mrcv : wrcv,
                    mesh ? fragME : fragWE,
                    mesh ? meb1 : web1, mesh ? meb2 : web2,
                    mesh ? meg : weg,   mesh ? mebt : webt,
                    mesh ? aggM : aggW, mesh ? outM : outW,
                    mesh ? EM : EW, r0, sm);
}

__global__ void __launch_bounds__(THREADS, 3)
node_kernel(const float* __restrict__ aggM, const float* __restrict__ aggW,
            const float* __restrict__ nf,
            const uint4* __restrict__ fragNM,
            const float* __restrict__ Pan,
            const float* __restrict__ b1, const float* __restrict__ b2,
            const float* __restrict__ gam, const float* __restrict__ bet,
            float* __restrict__ out) {
    extern __shared__ char sm[];
    mlp_block<false>(aggM, aggW, nf, Pan, nullptr, nullptr, nullptr,
                     fragNM, b1, b2, gam, bet, nullptr, out, NN,
                     blockIdx.x * MTILE, sm);
}

// ---------------- launch ----------------
extern "C" void kernel_launch(void* const* d_in, const int* in_sizes, int n_in,
                              void* d_out, int out_size) {
    (void)in_sizes; (void)n_in; (void)out_size;
    const float* nf   = (const float*)d_in[0];
    const int*   msnd = (const int*)d_in[1];
    const int*   mrcv = (const int*)d_in[2];
    const float* mf   = (const float*)d_in[3];
    const int*   wsnd = (const int*)d_in[4];
    const int*   wrcv = (const int*)d_in[5];
    const float* wf   = (const float*)d_in[6];

    const float* meW1 = (const float*)d_in[7];
    const float* meb1 = (const float*)d_in[8];
    const float* meW2 = (const float*)d_in[9];
    const float* meb2 = (const float*)d_in[10];
    const float* meg  = (const float*)d_in[11];
    const float* mebt = (const float*)d_in[12];

    const float* weW1 = (const float*)d_in[13];
    const float* web1 = (const float*)d_in[14];
    const float* weW2 = (const float*)d_in[15];
    const float* web2 = (const float*)d_in[16];
    const float* weg  = (const float*)d_in[17];
    const float* webt = (const float*)d_in[18];

    const float* nmW1 = (const float*)d_in[19];
    const float* nmb1 = (const float*)d_in[20];
    const float* nmW2 = (const float*)d_in[21];
    const float* nmb2 = (const float*)d_in[22];
    const float* nmg  = (const float*)d_in[23];
    const float* nmbt = (const float*)d_in[24];

    float* out       = (float*)d_out;
    float* out_nodes = out;
    float* out_mesh  = out + (size_t)NN * D;
    float* out_world = out_mesh + (size_t)EM * D;

    float *aggM = nullptr, *aggW = nullptr;
    float *Pam = nullptr, *Pbm = nullptr, *Paw = nullptr, *Pbw = nullptr, *Pan = nullptr;
    uint4* imgF = nullptr;
    cudaGetSymbolAddress((void**)&aggM, g_agg_mesh);
    cudaGetSymbolAddress((void**)&aggW, g_agg_world);
    cudaGetSymbolAddress((void**)&imgF, g_Wfrag);
    cudaGetSymbolAddress((void**)&Pam, g_Pam);
    cudaGetSymbolAddress((void**)&Pbm, g_Pbm);
    cudaGetSymbolAddress((void**)&Paw, g_Paw);
    cudaGetSymbolAddress((void**)&Pbw, g_Pbw);
    cudaGetSymbolAddress((void**)&Pan, g_Pan);
    uint4* fragME = imgF;
    uint4* fragWE = imgF + 16384;
    uint4* fragNM = imgF + 32768;

    cudaFuncSetAttribute(edge_kernel, cudaFuncAttributeMaxDynamicSharedMemorySize, SM_TOTAL);
    cudaFuncSetAttribute(node_kernel, cudaFuncAttributeMaxDynamicSharedMemorySize, SM_TOTAL);
    cudaFuncSetAttribute(precompute_kernel, cudaFuncAttributeMaxDynamicSharedMemorySize, SM_TOTAL);

    // #0: weight image + agg zero
    prep_all_kernel<<<256, 256>>>(meW1, meW2, weW1, weW2, nmW1, nmW2, imgF, aggM, aggW);
    // #1: precompute mesh+world P (combos 0,1)
    precompute_kernel<<<2 * NODE_TILES, THREADS, SM_TOTAL>>>(
        nf, imgF, Pam, Pbm, Paw, Pbw, Pan, 0);
    // #2: precompute node P (combo 2)
    precompute_kernel<<<NODE_TILES, THREADS, SM_TOTAL>>>(
        nf, imgF, Pam, Pbm, Paw, Pbw, Pan, 2);
    // #3: fused mesh+world edge kernel (profiled)
    edge_kernel<<<MESH_BLOCKS + WORLD_BLOCKS, THREADS, SM_TOTAL>>>(
        mf, wf, msnd, mrcv, wsnd, wrcv,
        fragME, fragWE, Pam, Pbm, Paw, Pbw,
        meb1, meb2, meg, mebt, web1, web2, weg, webt,
        aggM, aggW, out_mesh, out_world);
    // #4: node kernel
    node_kernel<<<NODE_TILES, THREADS, SM_TOTAL>>>(
        aggM, aggW, nf, fragNM, Pan, nmb1, nmb2, nmg, nmbt, out_nodes);
}

// round 14
// speedup vs baseline: 1.2797x; 1.0020x over previous
#include <cuda_runtime.h>
#include <cuda_bf16.h>
#include <cstdint>

#define D 128
#define NN 100000
#define EM 400000
#define EW 200000
#define EPS 1e-5f
#define THREADS 256
#define MTILE 64
#define AST 72                    // A tile row stride in halves (+4 banks/row skew)
#define AHB 9216                  // A half-tile: 64 rows * 72 * 2B
#define MESH_BLOCKS (EM / MTILE)          // 6250
#define WORLD_BLOCKS (EW / MTILE)         // 3125
#define NODE_TILES ((NN + MTILE - 1) / MTILE) // 1563

// ---------------- smem layout (bytes), SM_TOTAL = 41984 -> 3 CTAs/SM ----------------
#define SM_A    0
#define SM_PP   18432
#define SM_CV   36864
#define SM_IDX  37888
#define SM_STAT 38400
#define SM_TOTAL 41984
#define HS_STRIDE 132             // hs: 64*132*4 = 33792 bytes at offset 0

// ---------------- device scratch ----------------
__device__ float g_agg_mesh[(size_t)NN * D];
__device__ float g_agg_world[(size_t)NN * D];
// fragment-ordered weight image: [3 mlp][8 chunk][8 ntile][4 ks][hi 32 uint4 | lo 32 uint4]
// chunk stride = 2048 uint4, mlp stride = 16384 uint4
__device__ uint4 g_Wfrag[3 * 256 * 64];
// precomputed first-layer partials: P = nf @ W1x  (fp32)
__device__ float g_Pam[(size_t)NN * D];
__device__ float g_Pbm[(size_t)NN * D];
__device__ float g_Paw[(size_t)NN * D];
__device__ float g_Pbw[(size_t)NN * D];
__device__ float g_Pan[(size_t)NN * D];

// ---------------- helpers ----------------
__device__ __forceinline__ uint32_t smem_u32(const void* p) {
    uint32_t a;
    asm("{ .reg .u64 t; cvta.to.shared.u64 t, %1; cvt.u32.u64 %0, t; }" : "=r"(a) : "l"(p));
    return a;
}
__device__ __forceinline__ void ldsm_x4(uint32_t r[4], uint32_t addr) {
    asm volatile("ldmatrix.sync.aligned.m8n8.x4.shared.b16 {%0,%1,%2,%3}, [%4];"
        : "=r"(r[0]), "=r"(r[1]), "=r"(r[2]), "=r"(r[3]) : "r"(addr));
}
#define MMA_BF16(d, a, b0, b1) \
    asm volatile("mma.sync.aligned.m16n8k16.row.col.f32.bf16.bf16.f32 " \
        "{%0,%1,%2,%3}, {%4,%5,%6,%7}, {%8,%9}, {%0,%1,%2,%3};" \
        : "+f"((d)[0]), "+f"((d)[1]), "+f"((d)[2]), "+f"((d)[3]) \
        : "r"((a)[0]), "r"((a)[1]), "r"((a)[2]), "r"((a)[3]), "r"(b0), "r"(b1))

__device__ __forceinline__ void split_pack(float x, float y, uint32_t& hp, uint32_t& lp) {
    __nv_bfloat16 h0 = __float2bfloat16(x);
    __nv_bfloat16 h1 = __float2bfloat16(y);
    __nv_bfloat16 l0 = __float2bfloat16(x - __bfloat162float(h0));
    __nv_bfloat16 l1 = __float2bfloat16(y - __bfloat162float(h1));
    hp = (uint32_t)__bfloat16_as_ushort(h0) | ((uint32_t)__bfloat16_as_ushort(h1) << 16);
    lp = (uint32_t)__bfloat16_as_ushort(l0) | ((uint32_t)__bfloat16_as_ushort(l1) << 16);
}

// one K=64 chunk: warp tile 32x32; A hi/lo via ldmatrix, B via LDG.128 from
// fragment image. pbl = img + chunk*2048 + wN*512 + lane.
__device__ __forceinline__ void gemm_chunk(uint32_t aH, uint32_t aL,
                                           const uint4* __restrict__ pbl,
                                           float acc[2][4][4],
                                           int wM, int lane) {
    const int i = lane & 7, sel = lane >> 3;
    const uint32_t aOff = (uint32_t)((wM * 32 + i + ((sel & 1) << 3)) * AST
                                     + ((sel >> 1) << 3)) * 2;
#pragma unroll
    for (int ks = 0; ks < 4; ks++) {
        const uint32_t kOff = aOff + ks * 32;
        uint32_t ah[2][4], al[2][4];
#pragma unroll
        for (int mt = 0; mt < 2; mt++) {
            uint32_t off = kOff + mt * (16 * AST * 2);
            ldsm_x4(ah[mt], aH + off);
            ldsm_x4(al[mt], aL + off);
        }
#pragma unroll
        for (int p = 0; p < 2; p++) {
            const uint4 bhv = __ldg(pbl + (p * 4 + ks) * 64);
            const uint4 blv = __ldg(pbl + (p * 4 + ks) * 64 + 32);
#pragma unroll
            for (int mt = 0; mt < 2; mt++) MMA_BF16(acc[mt][2 * p + 0], ah[mt], bhv.x, bhv.y);
#pragma unroll
            for (int mt = 0; mt < 2; mt++) MMA_BF16(acc[mt][2 * p + 1], ah[mt], bhv.z, bhv.w);
#pragma unroll
            for (int mt = 0; mt < 2; mt++) MMA_BF16(acc[mt][2 * p + 0], ah[mt], blv.x, blv.y);
#pragma unroll
            for (int mt = 0; mt < 2; mt++) MMA_BF16(acc[mt][2 * p + 1], ah[mt], blv.z, blv.w);
#pragma unroll
            for (int mt = 0; mt < 2; mt++) MMA_BF16(acc[mt][2 * p + 0], al[mt], bhv.x, bhv.y);
#pragma unroll
            for (int mt = 0; mt < 2; mt++) MMA_BF16(acc[mt][2 * p + 1], al[mt], bhv.z, bhv.w);
        }
    }
}

// gather 64 fp32 rows x 64 cols from f (row-major, stride D), split to bf16
// hi/lo planes in smem buffer (plain stores)
__device__ __forceinline__ void stage_f32(const float* __restrict__ f, int col0,
                                          int r0, int nRows, char* sm, int bufOff,
                                          int tid) {
#pragma unroll
    for (int j = 0; j < 4; j++) {
        int e = j * THREADS + tid;
        int row = e >> 4, f4 = e & 15;
        int gr = r0 + row;
        if (gr >= nRows) gr = nRows - 1;
        float4 v = *(const float4*)(f + (size_t)gr * D + col0 + f4 * 4);
        uint32_t h0, l0, h1, l1;
        split_pack(v.x, v.y, h0, l0);
        split_pack(v.z, v.w, h1, l1);
        uint32_t off = (uint32_t)(row * AST + f4 * 4) * 2;
        *(uint2*)(sm + bufOff + off) = make_uint2(h0, h1);
        *(uint2*)(sm + bufOff + AHB + off) = make_uint2(l0, l1);
    }
}

// ---------------- prep: fragment-ordered weight image + agg zero ----------------
__global__ void prep_all_kernel(const float* __restrict__ W1a, const float* __restrict__ W2a,
                                const float* __restrict__ W1b, const float* __restrict__ W2b,
                                const float* __restrict__ W1c, const float* __restrict__ W2c,
                                uint4* __restrict__ imgF,
                                float* __restrict__ z0, float* __restrict__ z1) {
    int g = blockIdx.x * 256 + threadIdx.x;
    if (g < 24576) {
        int m = g >> 13;
        int r = g & 8191;
        int cts = r >> 5;        // (c*8 + t)*4 + ks
        int l = r & 31;
        int c = cts >> 5;
        int t = (cts >> 2) & 7;
        int ks = cts & 3;
        const float* W1 = m == 0 ? W1a : (m == 1 ? W1b : W1c);
        const float* W2 = m == 0 ? W2a : (m == 1 ? W2b : W2c);
        const float* W; int bk;
        if (c < 6) { W = W1; bk = c * 64; } else { W = W2; bk = (c - 6) * 64; }
        uint32_t hw[4], lw[4];
#pragma unroll
        for (int w = 0; w < 4; w++) {
            int n = t * 16 + (l >> 2) + ((w & 2) ? 8 : 0);
            int k = bk + ks * 16 + 2 * (l & 3) + ((w & 1) ? 8 : 0);
            float v0 = W[(size_t)k * 128 + n];
            float v1 = W[(size_t)(k + 1) * 128 + n];
            split_pack(v0, v1, hw[w], lw[w]);
        }
        size_t base = ((size_t)m * 256 + cts) * 64;
        imgF[base + l]      = make_uint4(hw[0], hw[1], hw[2], hw[3]);
        imgF[base + 32 + l] = make_uint4(lw[0], lw[1], lw[2], lw[3]);
    }
    float4 z = make_float4(0.f, 0.f, 0.f, 0.f);
    size_t n4 = (size_t)NN * D / 4;
    for (size_t i = g; i < n4; i += (size_t)gridDim.x * 256) {
        ((float4*)z0)[i] = z;
        ((float4*)z1)[i] = z;
    }
}

// ---------------- precompute: all 5 P arrays, nf staged ONCE per tile ----------------
// pass 0: mesh Pa (mlp0 chunks 0-1)   pass 1: mesh Pb (mlp0 chunks 2-3)
// pass 2: world Pa (mlp1 chunks 0-1)  pass 3: world Pb (mlp1 chunks 2-3)
// pass 4: node Pa (mlp2 chunks 0-1)
__global__ void __launch_bounds__(THREADS, 3)
precompute_kernel(const float* __restrict__ nf,
                  const uint4* __restrict__ imgF,
                  float* __restrict__ Pam, float* __restrict__ Pbm,
                  float* __restrict__ Paw, float* __restrict__ Pbw,
                  float* __restrict__ Pan) {
    extern __shared__ char sm[];
    int r0 = blockIdx.x * MTILE;

    const uint32_t smb = smem_u32(sm);
    const int tid = threadIdx.x;
    const int lane = tid & 31;
    const int wid = tid >> 5;
    const int wM = wid >> 2;
    const int wN = wid & 3;
    const int g4 = lane >> 2, cl = lane & 3;

    stage_f32(nf, 0,  r0, NN, sm, SM_A,  tid);
    stage_f32(nf, 64, r0, NN, sm, SM_PP, tid);
    __syncthreads();

    float* const Ptab[5] = { Pam, Pbm, Paw, Pbw, Pan };
#pragma unroll
    for (int pass = 0; pass < 5; pass++) {
        const int mlp = pass >> 1;
        const int c0 = (pass & 1) * 2;
        const uint4* pbl = imgF + (size_t)mlp * 16384 + wN * 512 + lane;
        float acc[2][4][4];
#pragma unroll
        for (int mt = 0; mt < 2; mt++)
#pragma unroll
            for (int nt = 0; nt < 4; nt++)
#pragma unroll
                for (int j = 0; j < 4; j++) acc[mt][nt][j] = 0.f;
        gemm_chunk(smb + SM_A,  smb + SM_A + AHB,  pbl + (c0 + 0) * 2048, acc, wM, lane);
        gemm_chunk(smb + SM_PP, smb + SM_PP + AHB, pbl + (c0 + 1) * 2048, acc, wM, lane);
        float* P = Ptab[pass];
#pragma unroll
        for (int mt = 0; mt < 2; mt++)
#pragma unroll
            for (int nt = 0; nt < 4; nt++)
#pragma unroll
                for (int h = 0; h < 2; h++) {
                    int row = wM * 32 + mt * 16 + h * 8 + g4;
                    int col = wN * 32 + nt * 8 + 2 * cl;
                    int gr = r0 + row;
                    if (gr < NN)
                        *(float2*)&P[(size_t)gr * D + col] =
                            make_float2(acc[mt][nt][2 * h], acc[mt][nt][2 * h + 1]);
                }
    }
}

// ---------------- fused MLP+LN block body ----------------
// EDGE:  GEMM1 = ef @ W1c (image chunks 4,5); then acc += Pa[s] + Pb[r].
// !EDGE: GEMM1 = aggM (img 2,3) + aggW (img 4,5); then acc += Pa[row].
template <bool EDGE>
__device__ __forceinline__ void mlp_block(
    const float* __restrict__ f1, const float* __restrict__ f2,
    const float* __restrict__ res,
    const float* __restrict__ Pa, const float* __restrict__ Pb,
    const int* __restrict__ senders, const int* __restrict__ receivers,
    const uint4* __restrict__ bimg,
    const float* __restrict__ b1, const float* __restrict__ b2,
    const float* __restrict__ gam, const float* __restrict__ bet,
    float* __restrict__ aggOut, float* __restrict__ out,
    int nRows, int r0, char* sm) {

    float* cv   = (float*)(sm + SM_CV);
    int*   sidx = (int*)(sm + SM_IDX);
    int*   ridx = sidx + MTILE;
    float* hs   = (float*)sm;

    const uint32_t smb = smem_u32(sm);
    const int tid = threadIdx.x;
    const int lane = tid & 31;
    const int wid = tid >> 5;
    const int wM = wid >> 2;       // 0..1
    const int wN = wid & 3;        // 0..3
    const int g4 = lane >> 2, cl = lane & 3;

    if (tid < 64) {
        int rr = r0 + tid;
        if (rr >= nRows) rr = nRows - 1;
        sidx[tid] = EDGE ? senders[rr] : rr;
        ridx[tid] = EDGE ? receivers[rr] : rr;
    } else if (tid >= 128) {
        int t = tid - 128;
        cv[t]       = b1[t];
        cv[128 + t] = b2[t];
    }
    __syncthreads();

    const uint4* pblBase = bimg + wN * 512 + lane;

    float acc[2][4][4];
#pragma unroll
    for (int mt = 0; mt < 2; mt++)
#pragma unroll
        for (int nt = 0; nt < 4; nt++)
#pragma unroll
            for (int j = 0; j < 4; j++) acc[mt][nt][j] = 0.f;

    // ================= GEMM1 (restructured: 1 sync per chunk, stage||mma) =====
    if (EDGE) {
        stage_f32(res, 0,  r0, nRows, sm, SM_A,  tid);
        stage_f32(res, 64, r0, nRows, sm, SM_PP, tid);
        __syncthreads();
        gemm_chunk(smb + SM_A,  smb + SM_A + AHB,  pblBase + 4 * 2048, acc, wM, lane);
        gemm_chunk(smb + SM_PP, smb + SM_PP + AHB, pblBase + 5 * 2048, acc, wM, lane);
    } else {
        stage_f32(f1, 0,  r0, nRows, sm, SM_A,  tid);
        stage_f32(f1, 64, r0, nRows, sm, SM_PP, tid);
        __syncthreads();
        gemm_chunk(smb + SM_A, smb + SM_A + AHB, pblBase + 2 * 2048, acc, wM, lane);
        __syncthreads();                       // buf0 free
        stage_f32(f2, 0, r0, nRows, sm, SM_A, tid);       // LDGs fly under next MMA
        gemm_chunk(smb + SM_PP, smb + SM_PP + AHB, pblBase + 3 * 2048, acc, wM, lane);
        __syncthreads();                       // buf1 free, buf0 staged
        stage_f32(f2, 64, r0, nRows, sm, SM_PP, tid);
        gemm_chunk(smb + SM_A, smb + SM_A + AHB, pblBase + 4 * 2048, acc, wM, lane);
        __syncthreads();                       // buf1 staged
        gemm_chunk(smb + SM_PP, smb + SM_PP + AHB, pblBase + 5 * 2048, acc, wM, lane);
    }
    __syncthreads();                           // all gemm reads done; buffers -> H

    // ================= acc += P gathers; h = relu(acc + b1) -> H =================
#pragma unroll
    for (int mt = 0; mt < 2; mt++)
#pragma unroll
        for (int nt = 0; nt < 4; nt++)
#pragma unroll
            for (int h = 0; h < 2; h++) {
                int row = wM * 32 + mt * 16 + h * 8 + g4;
                int col = wN * 32 + nt * 8 + 2 * cl;
                float2 pa = *(const float2*)&Pa[(size_t)sidx[row] * D + col];
                float v0 = acc[mt][nt][2 * h]     + pa.x;
                float v1 = acc[mt][nt][2 * h + 1] + pa.y;
                if (EDGE) {
                    float2 pb = *(const float2*)&Pb[(size_t)ridx[row] * D + col];
                    v0 += pb.x;
                    v1 += pb.y;
                }
                v0 = fmaxf(v0 + cv[col],     0.f);
                v1 = fmaxf(v1 + cv[col + 1], 0.f);
                uint32_t hp, lp;
                split_pack(v0, v1, hp, lp);
                int hc = col >> 6;
                uint32_t off = (uint32_t)(row * AST + (col & 63)) * 2;
                *(uint32_t*)(sm + hc * AHB + off) = hp;
                *(uint32_t*)(sm + SM_PP + hc * AHB + off) = lp;
            }
#pragma unroll
    for (int mt = 0; mt < 2; mt++)
#pragma unroll
        for (int nt = 0; nt < 4; nt++)
#pragma unroll
            for (int j = 0; j < 4; j++) acc[mt][nt][j] = 0.f;
    __syncthreads();

    // ================= GEMM2: image chunks 6,7 (A = H) =================
#pragma unroll
    for (int c2 = 0; c2 < 2; c2++) {
        gemm_chunk(smb + c2 * AHB, smb + SM_PP + c2 * AHB,
                   pblBase + (6 + c2) * 2048, acc, wM, lane);
    }
    __syncthreads();

    // ================= bias2 + LN stats =================
    float* statS = (float*)(sm + SM_STAT);          // [4][64]
    float* statQ = statS + 256;
    float* meanv = statQ + 256;                     // [64]
    float* rstdv = meanv + 64;
    float* sg    = rstdv + 64;                      // [128]
    float* sb    = sg + 128;

#pragma unroll
    for (int mt = 0; mt < 2; mt++)
#pragma unroll
        for (int nt = 0; nt < 4; nt++)
#pragma unroll
            for (int j = 0; j < 4; j++) {
                int col = wN * 32 + nt * 8 + 2 * cl + (j & 1);
                acc[mt][nt][j] += cv[128 + col];
            }
    if (tid < 128) {
        sg[tid] = gam[tid];
        sb[tid] = bet[tid];
    }
#pragma unroll
    for (int mt = 0; mt < 2; mt++)
#pragma unroll
        for (int h = 0; h < 2; h++) {
            float s = 0.f, q = 0.f;
#pragma unroll
            for (int nt = 0; nt < 4; nt++) {
                float v0 = acc[mt][nt][2 * h], v1 = acc[mt][nt][2 * h + 1];
                s += v0 + v1;
                q += v0 * v0 + v1 * v1;
            }
            s += __shfl_xor_sync(0xffffffffu, s, 1);
            s += __shfl_xor_sync(0xffffffffu, s, 2);
            q += __shfl_xor_sync(0xffffffffu, q, 1);
            q += __shfl_xor_sync(0xffffffffu, q, 2);
            if (cl == 0) {
                int r = wM * 32 + mt * 16 + h * 8 + g4;
                statS[wN * 64 + r] = s;
                statQ[wN * 64 + r] = q;
            }
        }
    __syncthreads();
    if (tid < 64) {
        float s = statS[tid] + statS[64 + tid] + statS[128 + tid] + statS[192 + tid];
        float q = statQ[tid] + statQ[64 + tid] + statQ[128 + tid] + statQ[192 + tid];
        float mean = s * (1.f / D);
        float var = q * (1.f / D) - mean * mean;
        meanv[tid] = mean;
        rstdv[tid] = rsqrtf(var + EPS);
    }
    __syncthreads();

    // ================= LN apply -> hs =================
#pragma unroll
    for (int mt = 0; mt < 2; mt++)
#pragma unroll
        for (int nt = 0; nt < 4; nt++)
#pragma unroll
            for (int j = 0; j < 4; j++) {
                int row = wM * 32 + mt * 16 + ((j >> 1) << 3) + g4;
                int col = wN * 32 + nt * 8 + 2 * cl + (j & 1);
                float y = sg[col] * (acc[mt][nt][j] - meanv[row]) * rstdv[row] + sb[col];
                hs[row * HS_STRIDE + col] = y;
            }
    __syncthreads();

    // ================= epilogue =================
#pragma unroll
    for (int j = 0; j < (MTILE * 32) / THREADS; j++) {
        int e = j * THREADS + tid;
        int r = e >> 5;
        int q = e & 31;
        int gr = r0 + r;
        if (gr < nRows) {
            float4 y = *(const float4*)&hs[r * HS_STRIDE + q * 4];
            size_t gi = (size_t)gr * D + q * 4;
            if (EDGE) {
                atomicAdd((float4*)&aggOut[(size_t)ridx[r] * D + q * 4], y);
            }
            float4 rv = *(const float4*)&res[gi];
            float4 o = make_float4(y.x + rv.x, y.y + rv.y, y.z + rv.z, y.w + rv.w);
            *(float4*)&out[gi] = o;
        }
    }
}

// ---------------- kernels ----------------
__global__ void __launch_bounds__(THREADS, 3)
edge_kernel(const float* __restrict__ mf, const float* __restrict__ wf,
            const int* __restrict__ msnd, const int* __restrict__ mrcv,
            const int* __restrict__ wsnd, const int* __restrict__ wrcv,
            const uint4* __restrict__ fragME, const uint4* __restrict__ fragWE,
            const float* __restrict__ Pam, const float* __restrict__ Pbm,
            const float* __restrict__ Paw, const float* __restrict__ Pbw,
            const float* __restrict__ meb1, const float* __restrict__ meb2,
            const float* __restrict__ meg,  const float* __restrict__ mebt,
            const float* __restrict__ web1, const float* __restrict__ web2,
            const float* __restrict__ weg,  const float* __restrict__ webt,
            float* __restrict__ aggM, float* __restrict__ aggW,
            float* __restrict__ outM, float* __restrict__ outW) {
    extern __shared__ char sm[];
    bool mesh = blockIdx.x < MESH_BLOCKS;
    int r0 = (mesh ? blockIdx.x : blockIdx.x - MESH_BLOCKS) * MTILE;
    mlp_block<true>(mesh ? mf : wf, nullptr, mesh ? mf : wf,
                    mesh ? Pam : Paw, mesh ? Pbm : Pbw,
                    mesh ? msnd : wsnd, mesh ? mrcv : wrcv,
                    mesh ? fragME : fragWE,
                    mesh ? meb1 : web1, mesh ? meb2 : web2,
                    mesh ? meg : weg,   mesh ? mebt : webt,
                    mesh ? aggM : aggW, mesh ? outM : outW,
                    mesh ? EM : EW, r0, sm);
}

__global__ void __launch_bounds__(THREADS, 3)
node_kernel(const float* __restrict__ aggM, const float* __restrict__ aggW,
            const float* __restrict__ nf,
            const uint4* __restrict__ fragNM,
            const float* __restrict__ Pan,
            const float* __restrict__ b1, const float* __restrict__ b2,
            const float* __restrict__ gam, const float* __restrict__ bet,
            float* __restrict__ out) {
    extern __shared__ char sm[];
    mlp_block<false>(aggM, aggW, nf, Pan, nullptr, nullptr, nullptr,
                     fragNM, b1, b2, gam, bet, nullptr, out, NN,
                     blockIdx.x * MTILE, sm);
}

// ---------------- launch ----------------
extern "C" void kernel_launch(void* const* d_in, const int* in_sizes, int n_in,
                              void* d_out, int out_size) {
    (void)in_sizes; (void)n_in; (void)out_size;
    const float* nf   = (const float*)d_in[0];
    const int*   msnd = (const int*)d_in[1];
    const int*   mrcv = (const int*)d_in[2];
    const float* mf   = (const float*)d_in[3];
    const int*   wsnd = (const int*)d_in[4];
    const int*   wrcv = (const int*)d_in[5];
    const float* wf   = (const float*)d_in[6];

    const float* meW1 = (const float*)d_in[7];
    const float* meb1 = (const float*)d_in[8];
    const float* meW2 = (const float*)d_in[9];
    const float* meb2 = (const float*)d_in[10];
    const float* meg  = (const float*)d_in[11];
    const float* mebt = (const float*)d_in[12];

    const float* weW1 = (const float*)d_in[13];
    const float* web1 = (const float*)d_in[14];
    const float* weW2 = (const float*)d_in[15];
    const float* web2 = (const float*)d_in[16];
    const float* weg  = (const float*)d_in[17];
    const float* webt = (const float*)d_in[18];

    const float* nmW1 = (const float*)d_in[19];
    const float* nmb1 = (const float*)d_in[20];
    const float* nmW2 = (const float*)d_in[21];
    const float* nmb2 = (const float*)d_in[22];
    const float* nmg  = (const float*)d_in[23];
    const float* nmbt = (const float*)d_in[24];

    float* out       = (float*)d_out;
    float* out_nodes = out;
    float* out_mesh  = out + (size_t)NN * D;
    float* out_world = out_mesh + (size_t)EM * D;

    float *aggM = nullptr, *aggW = nullptr;
    float *Pam = nullptr, *Pbm = nullptr, *Paw = nullptr, *Pbw = nullptr, *Pan = nullptr;
    uint4* imgF = nullptr;
    cudaGetSymbolAddress((void**)&aggM, g_agg_mesh);
    cudaGetSymbolAddress((void**)&aggW, g_agg_world);
    cudaGetSymbolAddress((void**)&imgF, g_Wfrag);
    cudaGetSymbolAddress((void**)&Pam, g_Pam);
    cudaGetSymbolAddress((void**)&Pbm, g_Pbm);
    cudaGetSymbolAddress((void**)&Paw, g_Paw);
    cudaGetSymbolAddress((void**)&Pbw, g_Pbw);
    cudaGetSymbolAddress((void**)&Pan, g_Pan);
    uint4* fragME = imgF;
    uint4* fragWE = imgF + 16384;
    uint4* fragNM = imgF + 32768;

    cudaFuncSetAttribute(edge_kernel, cudaFuncAttributeMaxDynamicSharedMemorySize, SM_TOTAL);
    cudaFuncSetAttribute(node_kernel, cudaFuncAttributeMaxDynamicSharedMemorySize, SM_TOTAL);
    cudaFuncSetAttribute(precompute_kernel, cudaFuncAttributeMaxDynamicSharedMemorySize, SM_TOTAL);

    // #0: weight image + agg zero
    prep_all_kernel<<<256, 256>>>(meW1, meW2, weW1, weW2, nmW1, nmW2, imgF, aggM, aggW);
    // #1: all 5 P arrays, nf staged once per tile
    precompute_kernel<<<NODE_TILES, THREADS, SM_TOTAL>>>(
        nf, imgF, Pam, Pbm, Paw, Pbw, Pan);
    // #2: fused mesh+world edge kernel
    edge_kernel<<<MESH_BLOCKS + WORLD_BLOCKS, THREADS, SM_TOTAL>>>(
        mf, wf, msnd, mrcv, wsnd, wrcv,
        fragME, fragWE, Pam, Pbm, Paw, Pbw,
        meb1, meb2, meg, mebt, web1, web2, weg, webt,
        aggM, aggW, out_mesh, out_world);
    // #3: node kernel (profiled)
    node_kernel<<<NODE_TILES, THREADS, SM_TOTAL>>>(
        aggM, aggW, nf, fragNM, Pan, nmb1, nmb2, nmg, nmbt, out_nodes);
}